// round 11
// baseline (speedup 1.0000x reference)
#include <cuda_runtime.h>
#include <cuda_fp16.h>
#include <cstdint>

// LaplacianReg: B=32, V=65536, K=8, C=3
// result[b,v,c] = (d[b,v,c] + sum_k w[v,k]*d[b,idx[v,k],c])^2,  d = out - tgt
//
// fp16 scratch split into two arrays so each gather's two cache lines hash to
// independent L2 slices (bit 7 is transparent in the LTS hash, so a 256B-
// aligned row would serialize both lines on one slice):
//   seg0[v]: halfs 0..63  of row [c*32+b]  (128B, line-aligned)
//   seg1[v]: halfs 64..95                  (64B)
// Pass 2: 2 v per warp, one cp.async per (k,2v) covering both segments of
// both v via per-lane addresses; self row in the same async group.

#define BB 32
#define VV 65536
#define CC 3
#define KK 8
#define TILE_V 64
#define P1PAD 112      // pass-1 smem halfs per v row (224B, 16B-multiple)
#define P2PAD 100      // output staging floats per v row
#define SLOTB 384      // stage bytes per slot: [s0v0:128][s0v1:128][s1v0:64][s1v1:64]
#define SLOTS 9        // 8 neighbors + self
#define WBUF (SLOTS * SLOTB)   // 3456 B per warp

__device__ __align__(256) uint4 g_seg0[(size_t)VV * 8];  // 8.4 MB
__device__ __align__(256) uint4 g_seg1[(size_t)VV * 4];  // 4.2 MB

// ---------------- Pass 1: diff + fp16 convert + transpose ----------------
__global__ void __launch_bounds__(256) diff_transpose_kernel(
    const float* __restrict__ out_, const float* __restrict__ tgt_)
{
    __shared__ __half s[TILE_V * P1PAD];

    const int tid = threadIdx.x;
    const int v0  = blockIdx.x * TILE_V;

#pragma unroll
    for (int it = 0; it < 6; it++) {
        int r4   = tid + it * 256;          // 0..1535
        int b    = r4 / 48;
        int off4 = r4 - b * 48;
        const float4* o4 = (const float4*)(out_ + (size_t)b * (VV * CC) + (size_t)v0 * CC);
        const float4* t4 = (const float4*)(tgt_ + (size_t)b * (VV * CC) + (size_t)v0 * CC);
        float4 o = o4[off4];
        float4 t = t4[off4];
        float d[4] = { o.x - t.x, o.y - t.y, o.z - t.z, o.w - t.w };
        int off = off4 * 4;                 // 0..191 = v_local*3 + c
#pragma unroll
        for (int j = 0; j < 4; j++) {
            int oo = off + j;
            int vl = oo / 3;
            int c  = oo - vl * 3;
            s[vl * P1PAD + c * 32 + b] = __float2half_rn(d[j]);
        }
    }
    __syncthreads();

    // seg0: 64 rows x 8 uint4, contiguous
    uint4* g0 = g_seg0 + (size_t)v0 * 8;
#pragma unroll
    for (int it = 0; it < 2; it++) {
        int f  = tid + it * 256;            // 0..511
        int vl = f >> 3;
        int q  = f & 7;
        g0[f] = *(const uint4*)(s + vl * P1PAD + q * 8);
    }
    // seg1: 64 rows x 4 uint4, contiguous
    uint4* g1 = g_seg1 + (size_t)v0 * 4;
    {
        int f  = tid;                       // 0..255
        int vl = f >> 2;
        int q  = f & 3;
        g1[f] = *(const uint4*)(s + vl * P1PAD + 64 + q * 8);
    }
}

// ---------------- Pass 2: slice-split cp.async gather ----------------
// block 256 = 8 warps; warp handles 2 v; block handles 16 v.
__global__ void __launch_bounds__(256) lap_kernel(
    const int* __restrict__ nidx, const float* __restrict__ nw,
    float* __restrict__ res)
{
    __shared__ __align__(16) char stage[8 * WBUF];   // 27648 B (also output staging)
    __shared__ int   si[128];
    __shared__ float sw[128];

    const int tid = threadIdx.x;
    const int v0  = blockIdx.x * 16;

    if (tid < 128) {
        si[tid] = nidx[v0 * KK + tid];
    } else {
        sw[tid - 128] = nw[v0 * KK + (tid - 128)];
    }
    __syncthreads();

    const int lane = tid & 31;
    const int wrp  = tid >> 5;

    if (lane < 24) {
        // producer lane class: which v of the pair, which segment, sub-offset
        const int idxv = (lane < 8) ? 0 : (lane < 16) ? 1 : (lane < 20) ? 0 : 1;
        const int inS1 = (lane >= 16);
        const int subq = inS1 ? (lane & 3) : (lane & 7);   // uint4 index in segment
        const int vlp  = wrp * 2 + idxv;
        const int vsel = v0 + vlp;

        const unsigned int stW = (unsigned int)__cvta_generic_to_shared(stage)
                                 + wrp * WBUF;
        const unsigned int dlane = stW + lane * 16;        // linear slot layout

        const int* ip = si + vlp * KK;
#pragma unroll
        for (int k = 0; k < KK; k++) {
            int nk = ip[k];
            const void* src = inS1
                ? (const void*)(g_seg1 + (size_t)nk * 4 + subq)
                : (const void*)(g_seg0 + (size_t)nk * 8 + subq);
            asm volatile("cp.async.cg.shared.global [%0], [%1], 16;\n"
                         :: "r"(dlane + k * SLOTB), "l"(src));
        }
        // self row -> slot 8
        {
            const void* src = inS1
                ? (const void*)(g_seg1 + (size_t)vsel * 4 + subq)
                : (const void*)(g_seg0 + (size_t)vsel * 8 + subq);
            asm volatile("cp.async.cg.shared.global [%0], [%1], 16;\n"
                         :: "r"(dlane + 8 * SLOTB), "l"(src));
        }
        asm volatile("cp.async.commit_group;\n");
        asm volatile("cp.async.wait_group 0;\n");

        // consumer lane class: g = v of pair, sub = 0..11 (8 halfs each)
        const int g   = (lane >= 12) ? 1 : 0;
        const int sub = lane - g * 12;
        const int vl  = wrp * 2 + g;
        const int off = (sub < 8) ? (g * 128 + sub * 16)
                                  : (256 + g * 64 + (sub - 8) * 16);
        const char* rb = stage + wrp * WBUF + off;

        // self row (weight 1)
        uint4 r = *(const uint4*)(rb + 8 * SLOTB);
        float2 p0 = __half22float2(*(__half2*)&r.x);
        float2 p1 = __half22float2(*(__half2*)&r.y);
        float2 p2 = __half22float2(*(__half2*)&r.z);
        float2 p3 = __half22float2(*(__half2*)&r.w);
        float a0 = p0.x, a1 = p0.y, a2 = p1.x, a3 = p1.y;
        float a4 = p2.x, a5 = p2.y, a6 = p3.x, a7 = p3.y;

        const float* wp = sw + vl * KK;
#pragma unroll
        for (int k = 0; k < KK; k++) {
            float wk = wp[k];
            uint4 q  = *(const uint4*)(rb + k * SLOTB);
            float2 q0 = __half22float2(*(__half2*)&q.x);
            float2 q1 = __half22float2(*(__half2*)&q.y);
            float2 q2 = __half22float2(*(__half2*)&q.z);
            float2 q3 = __half22float2(*(__half2*)&q.w);
            a0 = fmaf(wk, q0.x, a0);
            a1 = fmaf(wk, q0.y, a1);
            a2 = fmaf(wk, q1.x, a2);
            a3 = fmaf(wk, q1.y, a3);
            a4 = fmaf(wk, q2.x, a4);
            a5 = fmaf(wk, q2.y, a5);
            a6 = fmaf(wk, q3.x, a6);
            a7 = fmaf(wk, q3.y, a7);
        }

        // all reads of this warp's stage must complete before aliasing writes
        __syncwarp(0x00ffffffu);

        // stage squared results into the warp's own stage region (aliased):
        // warp region = 864 floats; row g at offset g*P2PAD, flat = c*32+b
        float* sws = (float*)(stage + wrp * WBUF) + g * P2PAD + sub * 8;
        float4 w1 = { a0 * a0, a1 * a1, a2 * a2, a3 * a3 };
        float4 w2 = { a4 * a4, a5 * a5, a6 * a6, a7 * a7 };
        *(float4*)(sws)     = w1;
        *(float4*)(sws + 4) = w2;
    }
    __syncthreads();

    // output (B,V,C): thread -> b = tid/8, vq = tid%8; two v per thread
    const float* sf = (const float*)stage;
    const int b  = tid >> 3;
    const int vq = tid & 7;
#pragma unroll
    for (int h = 0; h < 2; h++) {
        int vl = vq + h * 8;
        const float* sr = sf + (vl >> 1) * (WBUF / 4) + (vl & 1) * P2PAD + b;
        float r0 = sr[0];
        float r1 = sr[32];
        float r2 = sr[64];
        float* op = res + (size_t)b * (VV * CC) + (size_t)(v0 + vl) * CC;
        op[0] = r0;
        op[1] = r1;
        op[2] = r2;
    }
}

extern "C" void kernel_launch(void* const* d_in, const int* in_sizes, int n_in,
                              void* d_out, int out_size)
{
    const float* out_ = (const float*)d_in[0];
    const float* tgt_ = (const float*)d_in[1];
    const int*   nidx = (const int*)  d_in[2];
    const float* nw   = (const float*)d_in[3];
    float*       res  = (float*)d_out;

    diff_transpose_kernel<<<VV / TILE_V, 256>>>(out_, tgt_);
    lap_kernel<<<VV / 16, 256>>>(nidx, nw, res);
}

// round 12
// speedup vs baseline: 1.0715x; 1.0715x over previous
#include <cuda_runtime.h>
#include <cuda_fp16.h>
#include <cstdint>

// LaplacianReg: B=32, V=65536, K=8, C=3
// result[b,v,c] = (d[b,v,c] + sum_k w[v,k]*d[b,idx[v,k],c])^2,  d = out - tgt
//
// Pass 2: persistent 256-thread blocks, 8 tiles of 16 v each, double-buffered
// cp.async gathers (prefetch tile t+1 while computing tile t), all idx/weights
// preloaded to smem at prologue. Lane-private gather slots -> wait_group is the
// only gather sync. f32 accumulation over fp16 scratch.

#define BB 32
#define VV 65536
#define CC 3
#define KK 8
#define ROWQ 12        // uint4 per v (192B row)
#define TILE_V 64
#define P1PAD 104      // pass-1 smem halfs per v row
#define P2PAD 100      // out-stage floats per v row

#define TILES 8        // tiles per block (16 v each)
#define GRID2 512      // 512 * 8 * 16 = 65536 v
#define SLOTB 384      // bytes per slot (2 rows)
#define WBUF (9 * SLOTB)          // 3456 B per warp per buffer
#define STAGEB (8 * WBUF)         // 27648 B per buffer
// dynamic smem layout
#define OFF_IDX  (2 * STAGEB)             // 55296
#define OFF_W    (OFF_IDX + 4096)         // 59392
#define OFF_OUT  (OFF_W + 4096)           // 63488
#define DYN_TOTAL (OFF_OUT + 6400)        // 69888

// 12.6 MB fp16 scratch [v][c][b], uint4 for 16B alignment
__device__ uint4 g_diff_raw[(size_t)VV * ROWQ];

// ---------------- Pass 1: diff + fp16 convert + transpose ----------------
__global__ void __launch_bounds__(256) diff_transpose_kernel(
    const float* __restrict__ out_, const float* __restrict__ tgt_)
{
    __shared__ __half s[TILE_V * P1PAD];

    const int tid = threadIdx.x;
    const int v0  = blockIdx.x * TILE_V;

#pragma unroll
    for (int it = 0; it < 6; it++) {
        int r4   = tid + it * 256;          // 0..1535
        int b    = r4 / 48;
        int off4 = r4 - b * 48;
        const float4* o4 = (const float4*)(out_ + (size_t)b * (VV * CC) + (size_t)v0 * CC);
        const float4* t4 = (const float4*)(tgt_ + (size_t)b * (VV * CC) + (size_t)v0 * CC);
        float4 o = o4[off4];
        float4 t = t4[off4];
        float d[4] = { o.x - t.x, o.y - t.y, o.z - t.z, o.w - t.w };
        int off = off4 * 4;                 // 0..191 = v_local*3 + c
#pragma unroll
        for (int j = 0; j < 4; j++) {
            int oo = off + j;
            int vl = oo / 3;
            int c  = oo - vl * 3;
            s[vl * P1PAD + c * 32 + b] = __float2half_rn(d[j]);
        }
    }
    __syncthreads();

    uint4* gout = g_diff_raw + (size_t)v0 * ROWQ;
#pragma unroll
    for (int it = 0; it < 3; it++) {
        int f    = tid + it * 256;          // 0..767
        int vl   = f / ROWQ;
        int off  = f - vl * ROWQ;
        gout[f] = *(const uint4*)(s + vl * P1PAD + off * 8);
    }
}

// ---------------- Pass 2: persistent pipelined gather ----------------
__global__ void __launch_bounds__(256) lap_kernel(
    const int* __restrict__ nidx, const float* __restrict__ nw,
    float* __restrict__ res)
{
    extern __shared__ __align__(16) char dyn[];
    char*  stage  = dyn;
    int*   idxAll = (int*)  (dyn + OFF_IDX);   // [tile][vl][k] = nidx[B0*8 ..)
    float* wAll   = (float*)(dyn + OFF_W);
    float* outst  = (float*)(dyn + OFF_OUT);   // 16 * P2PAD floats

    const int tid  = threadIdx.x;
    const int lane = tid & 31;
    const int wrp  = tid >> 5;
    const int B0   = blockIdx.x * (TILES * 16);   // first v of this block

    // prologue: bulk-load all idx/weights for the block's 128 v (1024 each)
    ((int4*)idxAll)[tid]  = ((const int4*)(nidx + B0 * KK))[tid];
    ((float4*)wAll)[tid]  = ((const float4*)(nw   + B0 * KK))[tid];
    __syncthreads();

    const int g   = (lane >= 12) ? 1 : 0;
    const int sub = lane - g * 12;
    const int vl  = wrp * 2 + g;             // 0..15 within a tile
    const unsigned int stB = (unsigned int)__cvta_generic_to_shared(stage)
                             + wrp * WBUF + g * 192 + sub * 16;

#define ISSUE(T, BUF) do {                                                   \
    if (lane < 24) {                                                         \
        unsigned int d_ = stB + (BUF) * STAGEB;                              \
        const int* ipp = idxAll + (T) * 128 + vl * KK;                       \
        _Pragma("unroll")                                                    \
        for (int k_ = 0; k_ < KK; k_++) {                                    \
            int nk_ = ipp[k_];                                               \
            const void* s_ = (const void*)(g_diff_raw + (size_t)nk_ * ROWQ + sub); \
            asm volatile("cp.async.cg.shared.global [%0], [%1], 16;\n"       \
                         :: "r"(d_ + k_ * SLOTB), "l"(s_));                  \
        }                                                                    \
        {                                                                    \
            int nk_ = B0 + (T) * 16 + vl;                                    \
            const void* s_ = (const void*)(g_diff_raw + (size_t)nk_ * ROWQ + sub); \
            asm volatile("cp.async.cg.shared.global [%0], [%1], 16;\n"       \
                         :: "r"(d_ + 8 * SLOTB), "l"(s_));                   \
        }                                                                    \
    }                                                                        \
    asm volatile("cp.async.commit_group;\n");                                \
} while (0)

    ISSUE(0, 0);

    for (int t = 0; t < TILES; t++) {
        if (t < TILES - 1) {
            ISSUE(t + 1, (t + 1) & 1);
            asm volatile("cp.async.wait_group 1;\n");
        } else {
            asm volatile("cp.async.wait_group 0;\n");
        }

        if (lane < 24) {
            const char* rb = stage + (t & 1) * STAGEB + wrp * WBUF
                             + g * 192 + sub * 16;

            // self row (weight 1), slot 8
            uint4 r = *(const uint4*)(rb + 8 * SLOTB);
            float2 p0 = __half22float2(*(__half2*)&r.x);
            float2 p1 = __half22float2(*(__half2*)&r.y);
            float2 p2 = __half22float2(*(__half2*)&r.z);
            float2 p3 = __half22float2(*(__half2*)&r.w);
            float a0 = p0.x, a1 = p0.y, a2 = p1.x, a3 = p1.y;
            float a4 = p2.x, a5 = p2.y, a6 = p3.x, a7 = p3.y;

            const float* wp = wAll + t * 128 + vl * KK;
#pragma unroll
            for (int k = 0; k < KK; k++) {
                float wk = wp[k];
                uint4 q  = *(const uint4*)(rb + k * SLOTB);
                float2 q0 = __half22float2(*(__half2*)&q.x);
                float2 q1 = __half22float2(*(__half2*)&q.y);
                float2 q2 = __half22float2(*(__half2*)&q.z);
                float2 q3 = __half22float2(*(__half2*)&q.w);
                a0 = fmaf(wk, q0.x, a0);
                a1 = fmaf(wk, q0.y, a1);
                a2 = fmaf(wk, q1.x, a2);
                a3 = fmaf(wk, q1.y, a3);
                a4 = fmaf(wk, q2.x, a4);
                a5 = fmaf(wk, q2.y, a5);
                a6 = fmaf(wk, q3.x, a6);
                a7 = fmaf(wk, q3.y, a7);
            }

            float4 w1 = { a0 * a0, a1 * a1, a2 * a2, a3 * a3 };
            float4 w2 = { a4 * a4, a5 * a5, a6 * a6, a7 * a7 };
            *(float4*)(outst + vl * P2PAD + sub * 8)     = w1;
            *(float4*)(outst + vl * P2PAD + sub * 8 + 4) = w2;
        }
        __syncthreads();

        // output (B,V,C): thread -> b = tid/8, vq = tid%8; two v per thread
        {
            const int v0 = B0 + t * 16;
            const int b  = tid >> 3;
            const int vq = tid & 7;
#pragma unroll
            for (int h = 0; h < 2; h++) {
                int vv = vq + h * 8;
                const float* sr = outst + vv * P2PAD + b;
                float r0 = sr[0];
                float r1 = sr[32];
                float r2 = sr[64];
                float* op = res + (size_t)b * (VV * CC) + (size_t)(v0 + vv) * CC;
                op[0] = r0;
                op[1] = r1;
                op[2] = r2;
            }
        }
        __syncthreads();
    }
#undef ISSUE
}

extern "C" void kernel_launch(void* const* d_in, const int* in_sizes, int n_in,
                              void* d_out, int out_size)
{
    const float* out_ = (const float*)d_in[0];
    const float* tgt_ = (const float*)d_in[1];
    const int*   nidx = (const int*)  d_in[2];
    const float* nw   = (const float*)d_in[3];
    float*       res  = (float*)d_out;

    static bool attr_set = false;
    if (!attr_set) {
        cudaFuncSetAttribute(lap_kernel,
                             cudaFuncAttributeMaxDynamicSharedMemorySize,
                             DYN_TOTAL);
        attr_set = true;
    }

    diff_transpose_kernel<<<VV / TILE_V, 256>>>(out_, tgt_);
    lap_kernel<<<GRID2, 256, DYN_TOTAL>>>(nidx, nw, res);
}